// round 5
// baseline (speedup 1.0000x reference)
#include <cuda_runtime.h>
#include <cstddef>

// ---------------------------------------------------------------------------
// S4Layer: B=8, L=2048, D=1024
//   M = C_w @ A_w ; P = M @ Wx ; Q = M @ Wy ; c = M @ rc_b
//   u_t = x[:,t] @ P^T + c   (t = 1..2047)
//   y_0 = x[:,0] ;  y_t = u_t + Q y_{t-1}
// Chunked scan: 64 chunks of S=32.
//   pass1: w_k = sum_{j=1..32} Q^{32-j} u_{32k+j}   (chunks 0..62)
//   carry: c_0 = y_0 ; c_k = Q^32 c_{k-1} + w_{k-1}
//   pass2: y_{32k+s} = u + Q y_{32k+s-1}, seeded with c_k, in-place in d_out
// No host-side symbol queries: device buffers are selected device-side by id.
// ---------------------------------------------------------------------------

#define DM 1024
#define NB 8
#define LSEQ 2048
#define SCH 32
#define NCH 64
#define R1 504   // pass-1 rows = 63 chunks * 8 batch
#define R2 512   // pass-2 rows = 64 chunks * 8 batch

__device__ float g_M [DM * DM];
__device__ float g_P [DM * DM];
__device__ float g_Q [DM * DM];
__device__ float g_Wy[DM * DM];
__device__ float g_T1[DM * DM];
__device__ float g_T2[DM * DM];
__device__ float g_QS[DM * DM];
__device__ float g_cvec[DM];
__device__ float g_W0[R1 * DM];
__device__ float g_W1[R1 * DM];
__device__ float g_Cst[NCH * NB * DM];

// Buffer ids for the generic GEMM (resolved in device code; no
// cudaGetSymbolAddress anywhere).
#define BUF_M  0
#define BUF_P  1
#define BUF_Q  2
#define BUF_WY 3
#define BUF_T1 4
#define BUF_T2 5
#define BUF_QS 6

__device__ __forceinline__ float* sel_buf(int i)
{
    switch (i) {
        case BUF_M:  return g_M;
        case BUF_P:  return g_P;
        case BUF_Q:  return g_Q;
        case BUF_WY: return g_Wy;
        case BUF_T1: return g_T1;
        case BUF_T2: return g_T2;
        default:     return g_QS;
    }
}

// --------------------------------------------------------------------------
// Wy[k][d] = rc_w[k, D+d] + rc_w[k, 2D+d]
__global__ void k_prep_wy(const float* __restrict__ rc_w)
{
    int idx = blockIdx.x * blockDim.x + threadIdx.x;   // 1M elements
    int k = idx >> 10, d = idx & 1023;
    g_Wy[idx] = rc_w[k * 3072 + 1024 + d] + rc_w[k * 3072 + 2048 + d];
}

// --------------------------------------------------------------------------
// C (1024x1024) = A (1024x1024, row-major) @ B (1024xN slice, row-major ldb)
// Tiles: BM=64, BN=128, BK=16, 256 threads, 4x8 microtile per thread.
// A/B come from external pointers when ia/ib < 0, else device globals.
__global__ void __launch_bounds__(256)
k_gemm_g(const float* extA, const float* extB,
         int ia, int ib, int ic, int ldb)
{
    const float* A  = (ia >= 0) ? sel_buf(ia) : extA;
    const float* Bm = (ib >= 0) ? sel_buf(ib) : extB;
    float*       Cm = sel_buf(ic);

    __shared__ __align__(16) float As[16][68];
    __shared__ __align__(16) float Bs[16][132];
    const int tid = threadIdx.x;
    const int tx = tid & 15, ty = tid >> 4;
    const int row0 = blockIdx.y * 64, col0 = blockIdx.x * 128;

    float acc[4][8];
#pragma unroll
    for (int i = 0; i < 4; i++)
#pragma unroll
        for (int j = 0; j < 8; j++) acc[i][j] = 0.f;

    const int ar = tid >> 2;            // 0..63
    const int ak = (tid & 3) << 2;      // 0,4,8,12
    const int bn = (tid & 31) << 2;     // 0..124
    const int bk = tid >> 5;            // 0..7

    for (int k0 = 0; k0 < 1024; k0 += 16) {
        float4 av = *(const float4*)(A + (size_t)(row0 + ar) * 1024 + k0 + ak);
        As[ak + 0][ar] = av.x; As[ak + 1][ar] = av.y;
        As[ak + 2][ar] = av.z; As[ak + 3][ar] = av.w;
        float4 bv0 = *(const float4*)(Bm + (size_t)(k0 + bk) * ldb + col0 + bn);
        float4 bv1 = *(const float4*)(Bm + (size_t)(k0 + bk + 8) * ldb + col0 + bn);
        *(float4*)&Bs[bk][bn]     = bv0;
        *(float4*)&Bs[bk + 8][bn] = bv1;
        __syncthreads();
#pragma unroll
        for (int k = 0; k < 16; k++) {
            float a[4], b[8];
            *(float4*)a       = *(const float4*)&As[k][ty * 4];
            *(float4*)b       = *(const float4*)&Bs[k][tx * 8];
            *(float4*)(b + 4) = *(const float4*)&Bs[k][tx * 8 + 4];
#pragma unroll
            for (int i = 0; i < 4; i++)
#pragma unroll
                for (int j = 0; j < 8; j++) acc[i][j] += a[i] * b[j];
        }
        __syncthreads();
    }
#pragma unroll
    for (int i = 0; i < 4; i++) {
        float* crow = Cm + (size_t)(row0 + ty * 4 + i) * 1024 + col0 + tx * 8;
        *(float4*)crow       = make_float4(acc[i][0], acc[i][1], acc[i][2], acc[i][3]);
        *(float4*)(crow + 4) = make_float4(acc[i][4], acc[i][5], acc[i][6], acc[i][7]);
    }
}

// --------------------------------------------------------------------------
// g_cvec[e] = sum_k g_M[e,k] * rc_b[k]
__global__ void k_matvec_c(const float* __restrict__ rc_b)
{
    int e = blockIdx.x * 8 + (threadIdx.x >> 5);
    int lane = threadIdx.x & 31;
    const float* mr = g_M + (size_t)e * 1024;
    float acc = 0.f;
#pragma unroll 4
    for (int d = lane; d < 1024; d += 32) acc += mr[d] * rc_b[d];
#pragma unroll
    for (int o = 16; o > 0; o >>= 1) acc += __shfl_xor_sync(0xffffffffu, acc, o);
    if (lane == 0) g_cvec[e] = acc;
}

// --------------------------------------------------------------------------
// U[b,t,:] = x[b,t,:] @ P^T + c   (t = 1..2047), written into out.
// Row id rg in [0, 8*2047): b = rg/2047, t = 1 + rg%2047.
__global__ void __launch_bounds__(256)
k_gemm_u(const float* __restrict__ x, float* __restrict__ out)
{
    __shared__ __align__(16) float As[16][68];
    __shared__ __align__(16) float Bs[16][132];
    const int tid = threadIdx.x;
    const int tx = tid & 15, ty = tid >> 4;
    const int row0 = blockIdx.y * 64, col0 = blockIdx.x * 128;

    float acc[4][8];
#pragma unroll
    for (int i = 0; i < 4; i++)
#pragma unroll
        for (int j = 0; j < 8; j++) acc[i][j] = 0.f;

    const int ar = tid >> 2, ak = (tid & 3) << 2;
    const int bn0 = tid >> 2;     // 0..63, two passes of n

    int arg = row0 + ar;
    const float* arow;
    if (arg < NB * (LSEQ - 1)) {
        int b = arg / 2047, t = 1 + arg % 2047;
        arow = x + ((size_t)(b * 2048 + t)) * 1024;
    } else {
        arow = x;   // dummy, result discarded
    }

    for (int k0 = 0; k0 < 1024; k0 += 16) {
        float4 av = *(const float4*)(arow + k0 + ak);
        As[ak + 0][ar] = av.x; As[ak + 1][ar] = av.y;
        As[ak + 2][ar] = av.z; As[ak + 3][ar] = av.w;
#pragma unroll
        for (int p = 0; p < 2; p++) {
            int n = bn0 + p * 64;
            float4 bv = *(const float4*)(g_P + (size_t)(col0 + n) * 1024 + k0 + ak);
            Bs[ak + 0][n] = bv.x; Bs[ak + 1][n] = bv.y;
            Bs[ak + 2][n] = bv.z; Bs[ak + 3][n] = bv.w;
        }
        __syncthreads();
#pragma unroll
        for (int k = 0; k < 16; k++) {
            float a[4], b[8];
            *(float4*)a       = *(const float4*)&As[k][ty * 4];
            *(float4*)b       = *(const float4*)&Bs[k][tx * 8];
            *(float4*)(b + 4) = *(const float4*)&Bs[k][tx * 8 + 4];
#pragma unroll
            for (int i = 0; i < 4; i++)
#pragma unroll
                for (int j = 0; j < 8; j++) acc[i][j] += a[i] * b[j];
        }
        __syncthreads();
    }
#pragma unroll
    for (int i = 0; i < 4; i++) {
        int rg = row0 + ty * 4 + i;
        if (rg < NB * (LSEQ - 1)) {
            int b = rg / 2047, t = 1 + rg % 2047;
            float* crow = out + ((size_t)(b * 2048 + t)) * 1024 + col0 + tx * 8;
#pragma unroll
            for (int j = 0; j < 8; j++)
                crow[j] = acc[i][j] + g_cvec[col0 + tx * 8 + j];
        }
    }
}

// --------------------------------------------------------------------------
// out[b,0,:] = x[b,0,:] ; C[0] = y_0
__global__ void k_init(const float* __restrict__ x, float* __restrict__ out)
{
    int idx = blockIdx.x * blockDim.x + threadIdx.x;   // 8192
    int b = idx >> 10, e = idx & 1023;
    float v = x[((size_t)b * 2048) * 1024 + e];
    out[((size_t)b * 2048) * 1024 + e] = v;
    g_Cst[idx] = v;    // C[0][b][e], idx == b*1024+e
}

// --------------------------------------------------------------------------
// Pass 1 step s: w <- Q @ w + u_{32k+s} over chunks k=0..62 (504 rows).
// Double-buffered: step s reads (s odd? W0 : W1), writes the other.
__global__ void __launch_bounds__(256)
k_pass1(const float* __restrict__ u, int s)
{
    const float* Win = (s & 1) ? g_W0 : g_W1;
    float* Wout      = (s & 1) ? g_W1 : g_W0;
    __shared__ __align__(16) float As[16][68];
    __shared__ __align__(16) float Bs[16][68];
    const int tid = threadIdx.x;
    const int tx = tid & 15, ty = tid >> 4;
    const int row0 = blockIdx.y * 64, col0 = blockIdx.x * 64;

    float acc[4][4];
#pragma unroll
    for (int i = 0; i < 4; i++)
#pragma unroll
        for (int j = 0; j < 4; j++) acc[i][j] = 0.f;

    if (s > 1) {
        const int ar = tid >> 2, ak = (tid & 3) << 2;
        const int brn = tid >> 2;
        int arg = row0 + ar;
        const float* arow = (arg < R1) ? (Win + (size_t)arg * 1024) : 0;
        for (int k0 = 0; k0 < 1024; k0 += 16) {
            float4 av = arow ? *(const float4*)(arow + k0 + ak)
                             : make_float4(0.f, 0.f, 0.f, 0.f);
            As[ak + 0][ar] = av.x; As[ak + 1][ar] = av.y;
            As[ak + 2][ar] = av.z; As[ak + 3][ar] = av.w;
            float4 bv = *(const float4*)(g_Q + (size_t)(col0 + brn) * 1024 + k0 + ak);
            Bs[ak + 0][brn] = bv.x; Bs[ak + 1][brn] = bv.y;
            Bs[ak + 2][brn] = bv.z; Bs[ak + 3][brn] = bv.w;
            __syncthreads();
#pragma unroll
            for (int k = 0; k < 16; k++) {
                float a[4], b[4];
                *(float4*)a = *(const float4*)&As[k][ty * 4];
                *(float4*)b = *(const float4*)&Bs[k][tx * 4];
#pragma unroll
                for (int i = 0; i < 4; i++)
#pragma unroll
                    for (int j = 0; j < 4; j++) acc[i][j] += a[i] * b[j];
            }
            __syncthreads();
        }
    }
#pragma unroll
    for (int i = 0; i < 4; i++) {
        int rg = row0 + ty * 4 + i;
        if (rg < R1) {
            int ch = rg >> 3, b = rg & 7;
            int t = ch * SCH + s;
            const float* urow = u + ((size_t)(b * 2048 + t)) * 1024 + col0 + tx * 4;
            float* wrow = Wout + (size_t)rg * 1024 + col0 + tx * 4;
#pragma unroll
            for (int j = 0; j < 4; j++) wrow[j] = urow[j] + acc[i][j];
        }
    }
}

// --------------------------------------------------------------------------
// Carry chain: C[k] = W_end[k-1] + Q^32 @ C[k-1]. W_end = g_W0 (s=32 even).
// 64 blocks x 256 threads; each warp handles 2 output rows e, all 8 batches.
__global__ void k_carry(int k)
{
    int warp = threadIdx.x >> 5;            // 0..7
    int lane = threadIdx.x & 31;
    const float* cprev = g_Cst + (size_t)(k - 1) * 8192;
    const float* wrow  = g_W0 + (size_t)(k - 1) * 8192;
#pragma unroll
    for (int r = 0; r < 2; r++) {
        int e = blockIdx.x * 16 + warp * 2 + r;
        const float* qrow = g_QS + (size_t)e * 1024;
#pragma unroll
        for (int b = 0; b < 8; b++) {
            float acc = 0.f;
            const float* cp = cprev + b * 1024;
#pragma unroll 4
            for (int d = lane; d < 1024; d += 32) acc += qrow[d] * cp[d];
#pragma unroll
            for (int o = 16; o > 0; o >>= 1) acc += __shfl_xor_sync(0xffffffffu, acc, o);
            if (lane == 0)
                g_Cst[(size_t)k * 8192 + b * 1024 + e] = wrow[b * 1024 + e] + acc;
        }
    }
}

// --------------------------------------------------------------------------
// Pass 2 step s: y_{32k+s} = u_{32k+s} + Q @ y_{32k+s-1}, in place in out.
// s==1 seeds from carry buffer; chunk 63 s==32 (t=2048) is skipped.
__global__ void __launch_bounds__(256)
k_pass2(float* __restrict__ y, int s)
{
    __shared__ __align__(16) float As[16][68];
    __shared__ __align__(16) float Bs[16][68];
    const int tid = threadIdx.x;
    const int tx = tid & 15, ty = tid >> 4;
    const int row0 = blockIdx.y * 64, col0 = blockIdx.x * 64;

    float acc[4][4];
#pragma unroll
    for (int i = 0; i < 4; i++)
#pragma unroll
        for (int j = 0; j < 4; j++) acc[i][j] = 0.f;

    const int ar = tid >> 2, ak = (tid & 3) << 2;
    const int brn = tid >> 2;
    int arg = row0 + ar;                 // always < 512
    int ch_l = arg >> 3, b_l = arg & 7;
    int t_l = ch_l * SCH + s;
    const float* arow = (s == 1)
        ? (g_Cst + (size_t)arg * 1024)
        : (y + ((size_t)(b_l * 2048 + t_l - 1)) * 1024);   // t_l-1 <= 2047, always valid

    for (int k0 = 0; k0 < 1024; k0 += 16) {
        float4 av = *(const float4*)(arow + k0 + ak);
        As[ak + 0][ar] = av.x; As[ak + 1][ar] = av.y;
        As[ak + 2][ar] = av.z; As[ak + 3][ar] = av.w;
        float4 bv = *(const float4*)(g_Q + (size_t)(col0 + brn) * 1024 + k0 + ak);
        Bs[ak + 0][brn] = bv.x; Bs[ak + 1][brn] = bv.y;
        Bs[ak + 2][brn] = bv.z; Bs[ak + 3][brn] = bv.w;
        __syncthreads();
#pragma unroll
        for (int k = 0; k < 16; k++) {
            float a[4], b[4];
            *(float4*)a = *(const float4*)&As[k][ty * 4];
            *(float4*)b = *(const float4*)&Bs[k][tx * 4];
#pragma unroll
            for (int i = 0; i < 4; i++)
#pragma unroll
                for (int j = 0; j < 4; j++) acc[i][j] += a[i] * b[j];
        }
        __syncthreads();
    }
#pragma unroll
    for (int i = 0; i < 4; i++) {
        int rg = row0 + ty * 4 + i;
        int ch = rg >> 3, b = rg & 7;
        int t = ch * SCH + s;
        if (t < LSEQ) {
            float* yrow = y + ((size_t)(b * 2048 + t)) * 1024 + col0 + tx * 4;
#pragma unroll
            for (int j = 0; j < 4; j++) yrow[j] = yrow[j] + acc[i][j];
        }
    }
}

// --------------------------------------------------------------------------
extern "C" void kernel_launch(void* const* d_in, const int* in_sizes, int n_in,
                              void* d_out, int out_size)
{
    const float* x    = (const float*)d_in[0];
    const float* A_w  = (const float*)d_in[1];
    const float* C_w  = (const float*)d_in[2];
    const float* rc_w = (const float*)d_in[3];
    const float* rc_b = (const float*)d_in[4];
    float* out = (float*)d_out;

    dim3 gsq(8, 16);    // 1024x1024 NN gemm: 8 col-tiles x 16 row-tiles

    k_prep_wy<<<4096, 256>>>(rc_w);
    // M = C_w @ A_w
    k_gemm_g<<<gsq, 256>>>(C_w, A_w, -1, -1, BUF_M, 1024);
    // P = M @ Wx (Wx = rc_w[:, :1024], ldb = 3072)
    k_gemm_g<<<gsq, 256>>>(0, rc_w, BUF_M, -1, BUF_P, 3072);
    // Q = M @ Wy
    k_gemm_g<<<gsq, 256>>>(0, 0, BUF_M, BUF_WY, BUF_Q, 1024);
    // c = M @ rc_b
    k_matvec_c<<<128, 256>>>(rc_b);
    // U into d_out (t = 1..2047)
    k_gemm_u<<<dim3(8, 256), 256>>>(x, out);
    // Q^32 via 5 squarings
    k_gemm_g<<<gsq, 256>>>(0, 0, BUF_Q,  BUF_Q,  BUF_T1, 1024);
    k_gemm_g<<<gsq, 256>>>(0, 0, BUF_T1, BUF_T1, BUF_T2, 1024);
    k_gemm_g<<<gsq, 256>>>(0, 0, BUF_T2, BUF_T2, BUF_T1, 1024);
    k_gemm_g<<<gsq, 256>>>(0, 0, BUF_T1, BUF_T1, BUF_T2, 1024);
    k_gemm_g<<<gsq, 256>>>(0, 0, BUF_T2, BUF_T2, BUF_QS, 1024);
    // y_0 / C[0]
    k_init<<<32, 256>>>(x, out);
    // pass 1: chunk-local zero-init scans (only chunk-end sums kept)
    for (int s = 1; s <= SCH; s++)
        k_pass1<<<dim3(16, 8), 256>>>(out, s);
    // carry chain
    for (int k = 1; k < NCH; k++)
        k_carry<<<64, 256>>>(k);
    // pass 2: final scan, in place in d_out
    for (int s = 1; s <= SCH; s++)
        k_pass2<<<dim3(16, 8), 256>>>(out, s);
}